// round 4
// baseline (speedup 1.0000x reference)
#include <cuda_runtime.h>
#include <cuda_bf16.h>

// emdModule: brute-force NN (min/argmin over pairwise Euclidean distances)
// + 50-step price recurrence. Fully fused single kernel.
//
// Rounding model (BIT-EXACT vs the JAX reference — assignment tolerates ~zero
// argmin flips):
//   inner = fma(z,c, fma(y,b, x*a))        (XLA dot contraction, FMA chain)
//   d2    = fma(-2, inner, sq1 + sq2)      == (sq1+sq2) - 2*inner exactly
//   sq    = (x*x + y*y) + z*z              (elementwise squares, no fma)
//   cost  = sqrt(max(d2,0)) — monotone => min/argmin over raw d2
//   argmin: strict < => first index on ties (even/odd chains merged with
//           index-aware tie-break)
//   price recurrence: m = c_min - price; price += eps*m (separate rounded ops)
//
// f32x2 packed ops are two independent IEEE fp32 lanes => bit-identical to the
// scalar chain while halving issue count.

#define BATCH 16
#define NPTS 2048
#define ITILE 128                 // rows per block (1 per thread)
#define NPAIRS (NPTS / 2)         // 1024 candidate pairs (full j-range)
#define ITILES (NPTS / ITILE)     // 16
#define ROWS (BATCH * NPTS)       // 32768

typedef unsigned long long u64;

__device__ __forceinline__ u64 pk2(float lo, float hi) {
    u64 r; asm("mov.b64 %0, {%1, %2};" : "=l"(r) : "f"(lo), "f"(hi)); return r;
}
__device__ __forceinline__ void upk2(u64 v, float& lo, float& hi) {
    asm("mov.b64 {%0, %1}, %2;" : "=f"(lo), "=f"(hi) : "l"(v));
}
__device__ __forceinline__ u64 mul2(u64 a, u64 b) {
    u64 d; asm("mul.rn.f32x2 %0, %1, %2;" : "=l"(d) : "l"(a), "l"(b)); return d;
}
__device__ __forceinline__ u64 add2(u64 a, u64 b) {
    u64 d; asm("add.rn.f32x2 %0, %1, %2;" : "=l"(d) : "l"(a), "l"(b)); return d;
}
__device__ __forceinline__ u64 fma2(u64 a, u64 b, u64 c) {
    u64 d; asm("fma.rn.f32x2 %0, %1, %2, %3;" : "=l"(d) : "l"(a), "l"(b), "l"(c));
    return d;
}

__global__ void __launch_bounds__(ITILE) emd_fused_kernel(
    const float* __restrict__ x1, const float* __restrict__ x2,
    float* __restrict__ out,
    const float* __restrict__ eps_p, const int* __restrict__ iters_p,
    int write_assign) {
    int blk = blockIdx.x;
    int b   = blk / ITILES;           // batch
    int it  = blk % ITILES;           // i-tile

    // Pair-SoA staging of the FULL x2 set for this batch (2048 points, 32KB):
    //   tab_ab[p] = {a(2p), a(2p+1), b(2p), b(2p+1)}
    //   tab_cw[p] = {c(2p), c(2p+1), w(2p), w(2p+1)}
    // LDS.128 yields each operand PAIR in adjacent registers => b64 packed
    // operands at zero shuffle cost; all lanes read the same p (broadcast).
    __shared__ float4 tab_ab[NPAIRS];
    __shared__ float4 tab_cw[NPAIRS];
    const float* p2 = x2 + (long)b * NPTS * 3;
    for (int p = threadIdx.x; p < NPAIRS; p += ITILE) {
        float a0 = p2[6 * p + 0], b0 = p2[6 * p + 1], c0 = p2[6 * p + 2];
        float a1 = p2[6 * p + 3], b1 = p2[6 * p + 4], c1 = p2[6 * p + 5];
        float w0 = __fadd_rn(__fadd_rn(__fmul_rn(a0, a0), __fmul_rn(b0, b0)),
                             __fmul_rn(c0, c0));
        float w1 = __fadd_rn(__fadd_rn(__fmul_rn(a1, a1), __fmul_rn(b1, b1)),
                             __fmul_rn(c1, c1));
        tab_ab[p] = make_float4(a0, a1, b0, b1);
        tab_cw[p] = make_float4(c0, c1, w0, w1);
    }
    __syncthreads();

    int i = it * ITILE + threadIdx.x;
    const float* p1 = x1 + ((long)b * NPTS + i) * 3;
    float x = p1[0], y = p1[1], z = p1[2];
    float sq1 = __fadd_rn(__fadd_rn(__fmul_rn(x, x), __fmul_rn(y, y)),
                          __fmul_rn(z, z));

    u64 x2p = pk2(x, x), y2p = pk2(y, y), z2p = pk2(z, z);
    u64 s2p = pk2(sq1, sq1);
    u64 m2p = pk2(-2.0f, -2.0f);

    // Independent even/odd argmin chains (halves the serial FSETP->SEL dep).
    float best_lo = 3.4028235e38f, best_hi = 3.4028235e38f;
    int   bj_lo = 0, bj_hi = 1;
    #pragma unroll 8
    for (int p = 0; p < NPAIRS; p++) {
        float4 qab = tab_ab[p];
        float4 qcw = tab_cw[p];
        u64 a2 = pk2(qab.x, qab.y), b2 = pk2(qab.z, qab.w);
        u64 c2 = pk2(qcw.x, qcw.y), w2 = pk2(qcw.z, qcw.w);
        // Per lane: inner = fma(z,c, fma(y,b, x*a)); d2 = fma(-2, inner, sq1+w)
        u64 inner2 = fma2(z2p, c2, fma2(y2p, b2, mul2(x2p, a2)));
        u64 d2p    = fma2(m2p, inner2, add2(s2p, w2));
        float dlo, dhi;
        upk2(d2p, dlo, dhi);
        if (dlo < best_lo) { best_lo = dlo; bj_lo = 2 * p; }       // even js
        if (dhi < best_hi) { best_hi = dhi; bj_hi = 2 * p + 1; }   // odd js
    }

    // Merge chains: strict < keeps first index within each chain; across
    // chains, hi wins only if strictly smaller, or equal with smaller index.
    float best = best_lo; int bj = bj_lo;
    if (best_hi < best_lo || (best_hi == best_lo && bj_hi < bj_lo)) {
        best = best_hi; bj = bj_hi;
    }

    // Epilogue: clamp only the row minimum, sqrt, 50-step price recurrence.
    float cmin = sqrtf(fmaxf(best, 0.0f));              // IEEE sqrt
    float eps  = eps_p   ? *eps_p   : 0.005f;
    int   iters = iters_p ? *iters_p : 50;

    float price = 0.0f;
    float m = 0.0f;
    for (int t = 0; t < iters; t++) {
        m = __fadd_rn(cmin, -price);                    // c_min - price
        price = __fadd_rn(price, __fmul_rn(eps, m));    // price += eps*m
    }

    int row = b * NPTS + i;
    out[row] = sqrtf(m);
    if (write_assign) out[ROWS + row] = (float)bj;
}

extern "C" void kernel_launch(void* const* d_in, const int* in_sizes, int n_in,
                              void* d_out, int out_size) {
    const float* x1 = (const float*)d_in[0];
    const float* x2 = (const float*)d_in[1];
    const float* eps_p   = (n_in > 2) ? (const float*)d_in[2] : nullptr;
    const int*   iters_p = (n_in > 3) ? (const int*)d_in[3]   : nullptr;

    int write_assign = (out_size >= 2 * ROWS) ? 1 : 0;
    emd_fused_kernel<<<BATCH * ITILES, ITILE>>>(x1, x2, (float*)d_out,
                                                eps_p, iters_p, write_assign);
}

// round 5
// speedup vs baseline: 1.0756x; 1.0756x over previous
#include <cuda_runtime.h>
#include <cuda_bf16.h>

// emdModule: brute-force NN (min/argmin over pairwise Euclidean distances)
// + 50-step price recurrence. Single fused kernel, 4 threads per row.
//
// Rounding model (BIT-EXACT vs the JAX reference — assignment tolerates ~zero
// argmin flips):
//   inner = fma(z,c, fma(y,b, x*a))        (XLA dot contraction, FMA chain)
//   d2    = fma(-2, inner, sq1 + sq2)      == (sq1+sq2) - 2*inner exactly
//   sq    = (x*x + y*y) + z*z              (elementwise squares, no fma)
//   cost  = sqrt(max(d2,0)) — monotone => min/argmin over raw d2
//   argmin: strict < => first index on ties; cross-thread merge via packed
//           (bits(d2)<<32 | j) u64 min (positive-float bit order == value
//           order; low j bits => first-index tie-break)
//   price recurrence: m = c_min - price; price += eps*m (separate rounded ops)
//
// f32x2 packed ops are two independent IEEE fp32 lanes => bit-identical to the
// scalar chain while halving issue count. Operands are PRE-PACKED in smem as
// ulonglong2 so the hot loop has zero mov.b64 packing traffic.

#define BATCH 16
#define NPTS 2048
#define ITILE 128                 // rows per block
#define TPB 512                   // 4 threads per row (one per j-quarter)
#define NQUARTER 4
#define NPAIRS (NPTS / 2)         // 1024 candidate pairs total
#define QPAIRS (NPAIRS / NQUARTER) // 256 pairs per thread
#define ITILES (NPTS / ITILE)     // 16
#define ROWS (BATCH * NPTS)       // 32768

typedef unsigned long long u64;

__device__ __forceinline__ u64 pk2(float lo, float hi) {
    u64 r; asm("mov.b64 %0, {%1, %2};" : "=l"(r) : "f"(lo), "f"(hi)); return r;
}
__device__ __forceinline__ void upk2(u64 v, float& lo, float& hi) {
    asm("mov.b64 {%0, %1}, %2;" : "=f"(lo), "=f"(hi) : "l"(v));
}
__device__ __forceinline__ u64 mul2(u64 a, u64 b) {
    u64 d; asm("mul.rn.f32x2 %0, %1, %2;" : "=l"(d) : "l"(a), "l"(b)); return d;
}
__device__ __forceinline__ u64 add2(u64 a, u64 b) {
    u64 d; asm("add.rn.f32x2 %0, %1, %2;" : "=l"(d) : "l"(a), "l"(b)); return d;
}
__device__ __forceinline__ u64 fma2(u64 a, u64 b, u64 c) {
    u64 d; asm("fma.rn.f32x2 %0, %1, %2, %3;" : "=l"(d) : "l"(a), "l"(b), "l"(c));
    return d;
}

__global__ void __launch_bounds__(TPB, 2) emd_fused_kernel(
    const float* __restrict__ x1, const float* __restrict__ x2,
    float* __restrict__ out,
    const float* __restrict__ eps_p, const int* __restrict__ iters_p,
    int write_assign) {
    int blk = blockIdx.x;
    int b   = blk / ITILES;           // batch
    int it  = blk % ITILES;           // i-tile

    // Pre-packed pair-SoA staging of the FULL x2 set for this batch:
    //   tab_ab[p] = { pack(a(2p),a(2p+1)), pack(b(2p),b(2p+1)) }
    //   tab_cw[p] = { pack(c(2p),c(2p+1)), pack(w(2p),w(2p+1)) }
    // LDS.128 loads both packed 64-bit operands directly (broadcast: all
    // lanes read the same p -> conflict-free).
    __shared__ ulonglong2 tab_ab[NPAIRS];
    __shared__ ulonglong2 tab_cw[NPAIRS];
    __shared__ u64 part[TPB];

    int tid = threadIdx.x;
    int row_l = tid & (ITILE - 1);    // row within tile (0..127)
    int q     = tid >> 7;             // j-quarter (0..3)

    const float* p2 = x2 + (long)b * NPTS * 3;
    for (int p = tid; p < NPAIRS; p += TPB) {
        float a0 = p2[6 * p + 0], b0 = p2[6 * p + 1], c0 = p2[6 * p + 2];
        float a1 = p2[6 * p + 3], b1 = p2[6 * p + 4], c1 = p2[6 * p + 5];
        float w0 = __fadd_rn(__fadd_rn(__fmul_rn(a0, a0), __fmul_rn(b0, b0)),
                             __fmul_rn(c0, c0));
        float w1 = __fadd_rn(__fadd_rn(__fmul_rn(a1, a1), __fmul_rn(b1, b1)),
                             __fmul_rn(c1, c1));
        tab_ab[p] = make_ulonglong2(pk2(a0, a1), pk2(b0, b1));
        tab_cw[p] = make_ulonglong2(pk2(c0, c1), pk2(w0, w1));
    }
    __syncthreads();

    int i = it * ITILE + row_l;
    const float* p1 = x1 + ((long)b * NPTS + i) * 3;
    float x = p1[0], y = p1[1], z = p1[2];
    float sq1 = __fadd_rn(__fadd_rn(__fmul_rn(x, x), __fmul_rn(y, y)),
                          __fmul_rn(z, z));

    u64 x2p = pk2(x, x), y2p = pk2(y, y), z2p = pk2(z, z);
    u64 s2p = pk2(sq1, sq1);
    u64 m2p = pk2(-2.0f, -2.0f);

    // This thread scans pairs [q*QPAIRS, (q+1)*QPAIRS).
    // Independent even/odd argmin chains (halves the serial FSETP->SEL dep).
    float best_lo = 3.4028235e38f, best_hi = 3.4028235e38f;
    int   bj_lo = 0, bj_hi = 1;
    int p0 = q * QPAIRS;
    #pragma unroll 8
    for (int k = 0; k < QPAIRS; k++) {
        int p = p0 + k;
        ulonglong2 ab = tab_ab[p];
        ulonglong2 cw = tab_cw[p];
        // Per lane: inner = fma(z,c, fma(y,b, x*a)); d2 = fma(-2, inner, sq1+w)
        u64 inner2 = fma2(z2p, cw.x, fma2(y2p, ab.y, mul2(x2p, ab.x)));
        u64 d2p    = fma2(m2p, inner2, add2(s2p, cw.y));
        float dlo, dhi;
        upk2(d2p, dlo, dhi);
        if (dlo < best_lo) { best_lo = dlo; bj_lo = 2 * p; }       // even js
        if (dhi < best_hi) { best_hi = dhi; bj_hi = 2 * p + 1; }   // odd js
    }

    // Merge even/odd chains (index-aware on exact ties => first-index).
    float best = best_lo; int bj = bj_lo;
    if (best_hi < best_lo || (best_hi == best_lo && bj_hi < bj_lo)) {
        best = best_hi; bj = bj_hi;
    }

    // Clamp matches reference (max before min commutes; ties at 0 resolved by
    // smaller-j via the packed u64 min below).
    float dmin = fmaxf(best, 0.0f);
    part[tid] = ((u64)__float_as_uint(dmin) << 32) | (unsigned)bj;
    __syncthreads();

    // Threads 0..127: merge the 4 quarter-partials for their row + epilogue.
    if (tid < ITILE) {
        u64 key = part[tid];
        #pragma unroll
        for (int qq = 1; qq < NQUARTER; qq++) {
            u64 k2 = part[qq * ITILE + tid];
            if (k2 < key) key = k2;
        }
        float d2 = __uint_as_float((unsigned)(key >> 32));
        int   aj = (int)(key & 0xFFFFFFFFu);

        float cmin = sqrtf(d2);                         // IEEE sqrt (d2 >= 0)
        float eps  = eps_p   ? *eps_p   : 0.005f;
        int   iters = iters_p ? *iters_p : 50;

        float price = 0.0f;
        float m = 0.0f;
        for (int t = 0; t < iters; t++) {
            m = __fadd_rn(cmin, -price);                // c_min - price
            price = __fadd_rn(price, __fmul_rn(eps, m)); // price += eps*m
        }

        int row = b * NPTS + i;
        out[row] = sqrtf(m);
        if (write_assign) out[ROWS + row] = (float)aj;
    }
}

extern "C" void kernel_launch(void* const* d_in, const int* in_sizes, int n_in,
                              void* d_out, int out_size) {
    const float* x1 = (const float*)d_in[0];
    const float* x2 = (const float*)d_in[1];
    const float* eps_p   = (n_in > 2) ? (const float*)d_in[2] : nullptr;
    const int*   iters_p = (n_in > 3) ? (const int*)d_in[3]   : nullptr;

    int write_assign = (out_size >= 2 * ROWS) ? 1 : 0;
    emd_fused_kernel<<<BATCH * ITILES, TPB>>>(x1, x2, (float*)d_out,
                                              eps_p, iters_p, write_assign);
}